// round 3
// baseline (speedup 1.0000x reference)
#include <cuda_runtime.h>

#define BB 2
#define NN 2048
#define DIN 1024
#define DOUT 1024
#define HH 16
#define HD 64

// Scratch (static device allocations — allowed)
__device__ float g_q[BB*HH*NN*HD];
__device__ float g_k[BB*HH*NN*HD];
__device__ float g_v[BB*HH*NN*HD];
__device__ float g_ctx[BB*NN*DOUT];

// ---------------------------------------------------------------------------
// Fused QKV SGEMM: C = x @ W{q,k,v}, scattered into [b,h,n,d] layout.
// 128x128 block tile, TK=16, 256 threads, 8x8 micro-tile per thread.
// ---------------------------------------------------------------------------
__global__ __launch_bounds__(256) void qkv_gemm(
    const float* __restrict__ x,
    const float* __restrict__ Wq,
    const float* __restrict__ Wk,
    const float* __restrict__ Wv)
{
    const float* W = (blockIdx.z == 0) ? Wq : (blockIdx.z == 1 ? Wk : Wv);
    float* out = (blockIdx.z == 0) ? g_q : (blockIdx.z == 1 ? g_k : g_v);

    __shared__ float As[16][128];
    __shared__ float Bs[16][128];

    const int tid = threadIdx.x;
    const int bm = blockIdx.y * 128;
    const int bn = blockIdx.x * 128;
    const int tr = (tid >> 4) << 3;   // 0..120
    const int tc = (tid & 15) << 3;   // 0..120

    float acc[8][8];
    #pragma unroll
    for (int i = 0; i < 8; i++)
        #pragma unroll
        for (int j = 0; j < 8; j++) acc[i][j] = 0.f;

    for (int k0 = 0; k0 < DIN; k0 += 16) {
        // Load A tile (128 rows x 16 k), store transposed As[k][m]
        #pragma unroll
        for (int s = 0; s < 2; s++) {
            int slot = tid + s * 256;            // 0..511
            int r  = slot >> 2;                  // 0..127
            int c4 = (slot & 3) << 2;            // 0,4,8,12
            float4 v = *(const float4*)&x[(size_t)(bm + r) * DIN + k0 + c4];
            As[c4 + 0][r] = v.x; As[c4 + 1][r] = v.y;
            As[c4 + 2][r] = v.z; As[c4 + 3][r] = v.w;
        }
        // Load B tile (16 k x 128 n)
        #pragma unroll
        for (int s = 0; s < 2; s++) {
            int slot = tid + s * 256;
            int r  = slot >> 5;                  // 0..15
            int c4 = (slot & 31) << 2;           // 0..124
            *(float4*)&Bs[r][c4] = *(const float4*)&W[(size_t)(k0 + r) * DOUT + bn + c4];
        }
        __syncthreads();

        #pragma unroll
        for (int k = 0; k < 16; k++) {
            float a[8], b[8];
            #pragma unroll
            for (int i = 0; i < 8; i++) a[i] = As[k][tr + i];
            #pragma unroll
            for (int j = 0; j < 8; j++) b[j] = Bs[k][tc + j];
            #pragma unroll
            for (int i = 0; i < 8; i++)
                #pragma unroll
                for (int j = 0; j < 8; j++) acc[i][j] += a[i] * b[j];
        }
        __syncthreads();
    }

    // Epilogue: scatter to [b, h, n, d]
    #pragma unroll
    for (int i = 0; i < 8; i++) {
        int row = bm + tr + i;
        int b_ = row >> 11;        // row / 2048
        int n_ = row & 2047;
        #pragma unroll
        for (int j = 0; j < 8; j++) {
            int col = bn + tc + j;
            int h_ = col >> 6;
            int d_ = col & 63;
            out[(((size_t)(b_ * HH + h_) * NN) + n_) * HD + d_] = acc[i][j];
        }
    }
}

// ---------------------------------------------------------------------------
// Final SGEMM: d_out = g_ctx @ Wo + bo
// ---------------------------------------------------------------------------
__global__ __launch_bounds__(256) void out_gemm(
    const float* __restrict__ Wo,
    const float* __restrict__ bo,
    float* __restrict__ out)
{
    __shared__ float As[16][128];
    __shared__ float Bs[16][128];

    const int tid = threadIdx.x;
    const int bm = blockIdx.y * 128;
    const int bn = blockIdx.x * 128;
    const int tr = (tid >> 4) << 3;
    const int tc = (tid & 15) << 3;

    float acc[8][8];
    #pragma unroll
    for (int i = 0; i < 8; i++)
        #pragma unroll
        for (int j = 0; j < 8; j++) acc[i][j] = 0.f;

    for (int k0 = 0; k0 < DOUT; k0 += 16) {
        #pragma unroll
        for (int s = 0; s < 2; s++) {
            int slot = tid + s * 256;
            int r  = slot >> 2;
            int c4 = (slot & 3) << 2;
            float4 v = *(const float4*)&g_ctx[(size_t)(bm + r) * DOUT + k0 + c4];
            As[c4 + 0][r] = v.x; As[c4 + 1][r] = v.y;
            As[c4 + 2][r] = v.z; As[c4 + 3][r] = v.w;
        }
        #pragma unroll
        for (int s = 0; s < 2; s++) {
            int slot = tid + s * 256;
            int r  = slot >> 5;
            int c4 = (slot & 31) << 2;
            *(float4*)&Bs[r][c4] = *(const float4*)&Wo[(size_t)(k0 + r) * DOUT + bn + c4];
        }
        __syncthreads();

        #pragma unroll
        for (int k = 0; k < 16; k++) {
            float a[8], b[8];
            #pragma unroll
            for (int i = 0; i < 8; i++) a[i] = As[k][tr + i];
            #pragma unroll
            for (int j = 0; j < 8; j++) b[j] = Bs[k][tc + j];
            #pragma unroll
            for (int i = 0; i < 8; i++)
                #pragma unroll
                for (int j = 0; j < 8; j++) acc[i][j] += a[i] * b[j];
        }
        __syncthreads();
    }

    #pragma unroll
    for (int i = 0; i < 8; i++) {
        int row = bm + tr + i;
        #pragma unroll
        for (int j = 0; j < 8; j += 4) {
            int col = bn + tc + j;
            float4 bv = *(const float4*)&bo[col];
            float4 t;
            t.x = acc[i][j + 0] + bv.x;
            t.y = acc[i][j + 1] + bv.y;
            t.z = acc[i][j + 2] + bv.z;
            t.w = acc[i][j + 3] + bv.w;
            *(float4*)&out[(size_t)row * DOUT + col] = t;
        }
    }
}

// ---------------------------------------------------------------------------
// Attention: one thread per q-row, online softmax, K/V tiles of 32 in SMEM.
// scores = relu(q.k) * R_hat(r-k), causal, softmax(scores/8), ctx = attn @ v.
// R_hat = (1+exp(v)) / (1+exp(v - w*R)).
// Output written as [b, n, h*64+d] (row-major [4096, 1024]) for out_gemm.
// ---------------------------------------------------------------------------
__global__ __launch_bounds__(128) void attn_kernel(
    const float* __restrict__ wp,
    const float* __restrict__ vp)
{
    const int qb  = blockIdx.x;   // 0..15 (q tile of 128)
    const int h   = blockIdx.y;   // 0..15
    const int b   = blockIdx.z;   // 0..1
    const int tid = threadIdx.x;
    const int r   = qb * 128 + tid;   // this thread's q row

    const size_t head_off = (size_t)(b * HH + h) * NN * HD;
    const float* qbase = g_q + head_off;
    const float* kbase = g_k + head_off;
    const float* vbase = g_v + head_off;

    const float wh = wp[h];
    const float vh = vp[h];
    const float c1 = 1.f + __expf(vh);

    float qreg[64];
    #pragma unroll
    for (int i = 0; i < 16; i++) {
        float4 t = *(const float4*)&qbase[(size_t)r * HD + i * 4];
        qreg[i * 4 + 0] = t.x; qreg[i * 4 + 1] = t.y;
        qreg[i * 4 + 2] = t.z; qreg[i * 4 + 3] = t.w;
    }

    float acc[64];
    #pragma unroll
    for (int d = 0; d < 64; d++) acc[d] = 0.f;

    float m = -1e30f;
    float lsum = 0.f;

    __shared__ float Ks[32][64];
    __shared__ float Vs[32][64];

    const int ktiles = (qb + 1) * 4;   // k up to qb*128+127, tiles of 32

    for (int kt = 0; kt < ktiles; kt++) {
        const int k0 = kt * 32;
        // cooperative load of K/V tile: 32x64 floats each
        #pragma unroll
        for (int s = 0; s < 4; s++) {
            int slot = tid + s * 128;        // 0..511
            int rr  = slot >> 4;             // 0..31
            int c4  = (slot & 15) << 2;      // 0..60
            *(float4*)&Ks[rr][c4] = *(const float4*)&kbase[(size_t)(k0 + rr) * HD + c4];
            *(float4*)&Vs[rr][c4] = *(const float4*)&vbase[(size_t)(k0 + rr) * HD + c4];
        }
        __syncthreads();

        float l[32];
        float tmax = -1e30f;
        #pragma unroll
        for (int j = 0; j < 32; j++) {
            int kidx = k0 + j;
            float s = 0.f;
            #pragma unroll
            for (int d = 0; d < 64; d++) s += qreg[d] * Ks[j][d];
            s = fmaxf(s, 0.f);
            float R = (float)(r - kidx);
            float rhat = c1 / (1.f + __expf(vh - wh * R));
            float logit = s * rhat * 0.125f;
            l[j] = (kidx <= r) ? logit : -1e30f;
            tmax = fmaxf(tmax, l[j]);
        }

        float mnew  = fmaxf(m, tmax);
        float scale = __expf(m - mnew);
        lsum *= scale;
        #pragma unroll
        for (int d = 0; d < 64; d++) acc[d] *= scale;

        #pragma unroll
        for (int j = 0; j < 32; j++) {
            float p = __expf(l[j] - mnew);
            lsum += p;
            #pragma unroll
            for (int d = 0; d < 64; d++) acc[d] += p * Vs[j][d];
        }
        m = mnew;
        __syncthreads();
    }

    const float inv = 1.f / lsum;
    float* outp = g_ctx + ((size_t)(b * NN + r) * DOUT) + h * HD;
    #pragma unroll
    for (int i = 0; i < 16; i++) {
        float4 t;
        t.x = acc[i * 4 + 0] * inv;
        t.y = acc[i * 4 + 1] * inv;
        t.z = acc[i * 4 + 2] * inv;
        t.w = acc[i * 4 + 3] * inv;
        *(float4*)&outp[i * 4] = t;
    }
}

// ---------------------------------------------------------------------------
extern "C" void kernel_launch(void* const* d_in, const int* in_sizes, int n_in,
                              void* d_out, int out_size)
{
    const float* x  = (const float*)d_in[0];
    const float* Wq = (const float*)d_in[1];
    const float* Wk = (const float*)d_in[2];
    const float* Wv = (const float*)d_in[3];
    const float* Wo = (const float*)d_in[4];
    const float* bo = (const float*)d_in[5];
    const float* w  = (const float*)d_in[6];
    const float* v  = (const float*)d_in[7];
    float* out = (float*)d_out;

    // 1. QKV projections: [4096,1024] @ [1024,1024] x3
    dim3 g1(DOUT / 128, (BB * NN) / 128, 3);
    qkv_gemm<<<g1, 256>>>(x, Wq, Wk, Wv);

    // 2. Attention
    dim3 g2(NN / 128, HH, BB);
    attn_kernel<<<g2, 128>>>(w, v);

    // 3. Output projection + bias
    dim3 g3(DOUT / 128, (BB * NN) / 128, 1);
    out_gemm<<<g3, 256>>>(Wo, bo, out);
}

// round 4
// speedup vs baseline: 1.0055x; 1.0055x over previous
#include <cuda_runtime.h>

#define BB 2
#define NN 2048
#define DIN 1024
#define DOUT 1024
#define HH 16
#define HD 64

// Scratch (static device allocations — allowed)
__device__ float g_q[BB*HH*NN*HD];
__device__ float g_k[BB*HH*NN*HD];
__device__ float g_v[BB*HH*NN*HD];
__device__ float g_ctx[BB*NN*DOUT];

// ---------------------------------------------------------------------------
// Fused QKV SGEMM: C = x @ W{q,k,v}, scattered into [b,h,n,d] layout.
// 128x128 block tile, TK=16, 256 threads, 8x8 micro-tile per thread.
// ---------------------------------------------------------------------------
__global__ __launch_bounds__(256) void qkv_gemm(
    const float* __restrict__ x,
    const float* __restrict__ Wq,
    const float* __restrict__ Wk,
    const float* __restrict__ Wv)
{
    const float* W = (blockIdx.z == 0) ? Wq : (blockIdx.z == 1 ? Wk : Wv);
    float* out = (blockIdx.z == 0) ? g_q : (blockIdx.z == 1 ? g_k : g_v);

    __shared__ float As[16][128];
    __shared__ float Bs[16][128];

    const int tid = threadIdx.x;
    const int bm = blockIdx.y * 128;
    const int bn = blockIdx.x * 128;
    const int tr = (tid >> 4) << 3;   // 0..120
    const int tc = (tid & 15) << 3;   // 0..120

    float acc[8][8];
    #pragma unroll
    for (int i = 0; i < 8; i++)
        #pragma unroll
        for (int j = 0; j < 8; j++) acc[i][j] = 0.f;

    for (int k0 = 0; k0 < DIN; k0 += 16) {
        // Load A tile (128 rows x 16 k), store transposed As[k][m]
        #pragma unroll
        for (int s = 0; s < 2; s++) {
            int slot = tid + s * 256;            // 0..511
            int r  = slot >> 2;                  // 0..127
            int c4 = (slot & 3) << 2;            // 0,4,8,12
            float4 v = *(const float4*)&x[(size_t)(bm + r) * DIN + k0 + c4];
            As[c4 + 0][r] = v.x; As[c4 + 1][r] = v.y;
            As[c4 + 2][r] = v.z; As[c4 + 3][r] = v.w;
        }
        // Load B tile (16 k x 128 n)
        #pragma unroll
        for (int s = 0; s < 2; s++) {
            int slot = tid + s * 256;
            int r  = slot >> 5;                  // 0..15
            int c4 = (slot & 31) << 2;           // 0..124
            *(float4*)&Bs[r][c4] = *(const float4*)&W[(size_t)(k0 + r) * DOUT + bn + c4];
        }
        __syncthreads();

        #pragma unroll
        for (int k = 0; k < 16; k++) {
            float a[8], b[8];
            #pragma unroll
            for (int i = 0; i < 8; i++) a[i] = As[k][tr + i];
            #pragma unroll
            for (int j = 0; j < 8; j++) b[j] = Bs[k][tc + j];
            #pragma unroll
            for (int i = 0; i < 8; i++)
                #pragma unroll
                for (int j = 0; j < 8; j++) acc[i][j] += a[i] * b[j];
        }
        __syncthreads();
    }

    // Epilogue: scatter to [b, h, n, d]
    #pragma unroll
    for (int i = 0; i < 8; i++) {
        int row = bm + tr + i;
        int b_ = row >> 11;        // row / 2048
        int n_ = row & 2047;
        #pragma unroll
        for (int j = 0; j < 8; j++) {
            int col = bn + tc + j;
            int h_ = col >> 6;
            int d_ = col & 63;
            out[(((size_t)(b_ * HH + h_) * NN) + n_) * HD + d_] = acc[i][j];
        }
    }
}

// ---------------------------------------------------------------------------
// Final SGEMM: d_out = g_ctx @ Wo + bo
// ---------------------------------------------------------------------------
__global__ __launch_bounds__(256) void out_gemm(
    const float* __restrict__ Wo,
    const float* __restrict__ bo,
    float* __restrict__ out)
{
    __shared__ float As[16][128];
    __shared__ float Bs[16][128];

    const int tid = threadIdx.x;
    const int bm = blockIdx.y * 128;
    const int bn = blockIdx.x * 128;
    const int tr = (tid >> 4) << 3;
    const int tc = (tid & 15) << 3;

    float acc[8][8];
    #pragma unroll
    for (int i = 0; i < 8; i++)
        #pragma unroll
        for (int j = 0; j < 8; j++) acc[i][j] = 0.f;

    for (int k0 = 0; k0 < DOUT; k0 += 16) {
        #pragma unroll
        for (int s = 0; s < 2; s++) {
            int slot = tid + s * 256;
            int r  = slot >> 2;
            int c4 = (slot & 3) << 2;
            float4 v = *(const float4*)&g_ctx[(size_t)(bm + r) * DOUT + k0 + c4];
            As[c4 + 0][r] = v.x; As[c4 + 1][r] = v.y;
            As[c4 + 2][r] = v.z; As[c4 + 3][r] = v.w;
        }
        #pragma unroll
        for (int s = 0; s < 2; s++) {
            int slot = tid + s * 256;
            int r  = slot >> 5;
            int c4 = (slot & 31) << 2;
            *(float4*)&Bs[r][c4] = *(const float4*)&Wo[(size_t)(k0 + r) * DOUT + bn + c4];
        }
        __syncthreads();

        #pragma unroll
        for (int k = 0; k < 16; k++) {
            float a[8], b[8];
            #pragma unroll
            for (int i = 0; i < 8; i++) a[i] = As[k][tr + i];
            #pragma unroll
            for (int j = 0; j < 8; j++) b[j] = Bs[k][tc + j];
            #pragma unroll
            for (int i = 0; i < 8; i++)
                #pragma unroll
                for (int j = 0; j < 8; j++) acc[i][j] += a[i] * b[j];
        }
        __syncthreads();
    }

    #pragma unroll
    for (int i = 0; i < 8; i++) {
        int row = bm + tr + i;
        #pragma unroll
        for (int j = 0; j < 8; j += 4) {
            int col = bn + tc + j;
            float4 bv = *(const float4*)&bo[col];
            float4 t;
            t.x = acc[i][j + 0] + bv.x;
            t.y = acc[i][j + 1] + bv.y;
            t.z = acc[i][j + 2] + bv.z;
            t.w = acc[i][j + 3] + bv.w;
            *(float4*)&out[(size_t)row * DOUT + col] = t;
        }
    }
}

// ---------------------------------------------------------------------------
// Attention: one thread per q-row, online softmax, K/V tiles of 32 in SMEM.
// scores = relu(q.k) * R_hat(r-k), causal, softmax(scores/8), ctx = attn @ v.
// R_hat = (1+exp(v)) / (1+exp(v - w*R)).
// Output written as [b, n, h*64+d] (row-major [4096, 1024]) for out_gemm.
// ---------------------------------------------------------------------------
__global__ __launch_bounds__(128) void attn_kernel(
    const float* __restrict__ wp,
    const float* __restrict__ vp)
{
    const int qb  = blockIdx.x;   // 0..15 (q tile of 128)
    const int h   = blockIdx.y;   // 0..15
    const int b   = blockIdx.z;   // 0..1
    const int tid = threadIdx.x;
    const int r   = qb * 128 + tid;   // this thread's q row

    const size_t head_off = (size_t)(b * HH + h) * NN * HD;
    const float* qbase = g_q + head_off;
    const float* kbase = g_k + head_off;
    const float* vbase = g_v + head_off;

    const float wh = wp[h];
    const float vh = vp[h];
    const float c1 = 1.f + __expf(vh);

    float qreg[64];
    #pragma unroll
    for (int i = 0; i < 16; i++) {
        float4 t = *(const float4*)&qbase[(size_t)r * HD + i * 4];
        qreg[i * 4 + 0] = t.x; qreg[i * 4 + 1] = t.y;
        qreg[i * 4 + 2] = t.z; qreg[i * 4 + 3] = t.w;
    }

    float acc[64];
    #pragma unroll
    for (int d = 0; d < 64; d++) acc[d] = 0.f;

    float m = -1e30f;
    float lsum = 0.f;

    __shared__ float Ks[32][64];
    __shared__ float Vs[32][64];

    const int ktiles = (qb + 1) * 4;   // k up to qb*128+127, tiles of 32

    for (int kt = 0; kt < ktiles; kt++) {
        const int k0 = kt * 32;
        // cooperative load of K/V tile: 32x64 floats each
        #pragma unroll
        for (int s = 0; s < 4; s++) {
            int slot = tid + s * 128;        // 0..511
            int rr  = slot >> 4;             // 0..31
            int c4  = (slot & 15) << 2;      // 0..60
            *(float4*)&Ks[rr][c4] = *(const float4*)&kbase[(size_t)(k0 + rr) * HD + c4];
            *(float4*)&Vs[rr][c4] = *(const float4*)&vbase[(size_t)(k0 + rr) * HD + c4];
        }
        __syncthreads();

        float l[32];
        float tmax = -1e30f;
        #pragma unroll
        for (int j = 0; j < 32; j++) {
            int kidx = k0 + j;
            float s = 0.f;
            #pragma unroll
            for (int d = 0; d < 64; d++) s += qreg[d] * Ks[j][d];
            s = fmaxf(s, 0.f);
            float R = (float)(r - kidx);
            float rhat = c1 / (1.f + __expf(vh - wh * R));
            float logit = s * rhat * 0.125f;
            l[j] = (kidx <= r) ? logit : -1e30f;
            tmax = fmaxf(tmax, l[j]);
        }

        float mnew  = fmaxf(m, tmax);
        float scale = __expf(m - mnew);
        lsum *= scale;
        #pragma unroll
        for (int d = 0; d < 64; d++) acc[d] *= scale;

        #pragma unroll
        for (int j = 0; j < 32; j++) {
            float p = __expf(l[j] - mnew);
            lsum += p;
            #pragma unroll
            for (int d = 0; d < 64; d++) acc[d] += p * Vs[j][d];
        }
        m = mnew;
        __syncthreads();
    }

    const float inv = 1.f / lsum;
    float* outp = g_ctx + ((size_t)(b * NN + r) * DOUT) + h * HD;
    #pragma unroll
    for (int i = 0; i < 16; i++) {
        float4 t;
        t.x = acc[i * 4 + 0] * inv;
        t.y = acc[i * 4 + 1] * inv;
        t.z = acc[i * 4 + 2] * inv;
        t.w = acc[i * 4 + 3] * inv;
        *(float4*)&outp[i * 4] = t;
    }
}

// ---------------------------------------------------------------------------
extern "C" void kernel_launch(void* const* d_in, const int* in_sizes, int n_in,
                              void* d_out, int out_size)
{
    const float* x  = (const float*)d_in[0];
    const float* Wq = (const float*)d_in[1];
    const float* Wk = (const float*)d_in[2];
    const float* Wv = (const float*)d_in[3];
    const float* Wo = (const float*)d_in[4];
    const float* bo = (const float*)d_in[5];
    const float* w  = (const float*)d_in[6];
    const float* v  = (const float*)d_in[7];
    float* out = (float*)d_out;

    // 1. QKV projections: [4096,1024] @ [1024,1024] x3
    dim3 g1(DOUT / 128, (BB * NN) / 128, 3);
    qkv_gemm<<<g1, 256>>>(x, Wq, Wk, Wv);

    // 2. Attention
    dim3 g2(NN / 128, HH, BB);
    attn_kernel<<<g2, 128>>>(w, v);

    // 3. Output projection + bias
    dim3 g3(DOUT / 128, (BB * NN) / 128, 1);
    out_gemm<<<g3, 256>>>(Wo, bo, out);
}

// round 5
// speedup vs baseline: 1.0105x; 1.0049x over previous
#include <cuda_runtime.h>

#define BB 2
#define NN 2048
#define DIN 1024
#define DOUT 1024
#define HH 16
#define HD 64

// Scratch (static device allocations — allowed)
__device__ float g_q[BB*HH*NN*HD];
__device__ float g_k[BB*HH*NN*HD];
__device__ float g_v[BB*HH*NN*HD];
__device__ float g_ctx[BB*NN*DOUT];

// ---------------------------------------------------------------------------
// Fused QKV SGEMM: C = x @ W{q,k,v}, scattered into [b,h,n,d] layout.
// 128x128 block tile, TK=16, 256 threads, 8x8 micro-tile, double-buffered SMEM
// with global->register prefetch (1 __syncthreads per K-tile).
// ---------------------------------------------------------------------------
__global__ __launch_bounds__(256) void qkv_gemm(
    const float* __restrict__ x,
    const float* __restrict__ Wq,
    const float* __restrict__ Wk,
    const float* __restrict__ Wv)
{
    const float* W = (blockIdx.z == 0) ? Wq : (blockIdx.z == 1 ? Wk : Wv);
    float* out = (blockIdx.z == 0) ? g_q : (blockIdx.z == 1 ? g_k : g_v);

    __shared__ float As[2][16][128];
    __shared__ float Bs[2][16][128];

    const int tid = threadIdx.x;
    const int bm = blockIdx.y * 128;
    const int bn = blockIdx.x * 128;
    const int tr = (tid >> 4) << 3;
    const int tc = (tid & 15) << 3;

    // load-slot geometry (2 slots per thread, each a float4)
    int a_r[2], a_c[2], b_r[2], b_c[2];
    #pragma unroll
    for (int s = 0; s < 2; s++) {
        int slot = tid + s * 256;        // 0..511
        a_r[s] = slot >> 2;              // 0..127
        a_c[s] = (slot & 3) << 2;        // 0,4,8,12
        b_r[s] = slot >> 5;              // 0..15
        b_c[s] = (slot & 31) << 2;       // 0..124
    }

    float acc[8][8];
    #pragma unroll
    for (int i = 0; i < 8; i++)
        #pragma unroll
        for (int j = 0; j < 8; j++) acc[i][j] = 0.f;

    // prologue: tile 0 into buffer 0
    #pragma unroll
    for (int s = 0; s < 2; s++) {
        float4 va = *(const float4*)&x[(size_t)(bm + a_r[s]) * DIN + a_c[s]];
        As[0][a_c[s] + 0][a_r[s]] = va.x; As[0][a_c[s] + 1][a_r[s]] = va.y;
        As[0][a_c[s] + 2][a_r[s]] = va.z; As[0][a_c[s] + 3][a_r[s]] = va.w;
        *(float4*)&Bs[0][b_r[s]][b_c[s]] =
            *(const float4*)&W[(size_t)b_r[s] * DOUT + bn + b_c[s]];
    }
    __syncthreads();

    int buf = 0;
    const int NKT = DIN / 16;
    for (int kt = 0; kt < NKT; kt++) {
        float4 pa[2], pb[2];
        if (kt < NKT - 1) {
            int k0n = (kt + 1) * 16;
            #pragma unroll
            for (int s = 0; s < 2; s++) {
                pa[s] = *(const float4*)&x[(size_t)(bm + a_r[s]) * DIN + k0n + a_c[s]];
                pb[s] = *(const float4*)&W[(size_t)(k0n + b_r[s]) * DOUT + bn + b_c[s]];
            }
        }

        #pragma unroll
        for (int k = 0; k < 16; k++) {
            float a[8], b[8];
            #pragma unroll
            for (int i = 0; i < 8; i++) a[i] = As[buf][k][tr + i];
            #pragma unroll
            for (int j = 0; j < 8; j++) b[j] = Bs[buf][k][tc + j];
            #pragma unroll
            for (int i = 0; i < 8; i++)
                #pragma unroll
                for (int j = 0; j < 8; j++) acc[i][j] += a[i] * b[j];
        }

        if (kt < NKT - 1) {
            int nb = buf ^ 1;
            #pragma unroll
            for (int s = 0; s < 2; s++) {
                As[nb][a_c[s] + 0][a_r[s]] = pa[s].x;
                As[nb][a_c[s] + 1][a_r[s]] = pa[s].y;
                As[nb][a_c[s] + 2][a_r[s]] = pa[s].z;
                As[nb][a_c[s] + 3][a_r[s]] = pa[s].w;
                *(float4*)&Bs[nb][b_r[s]][b_c[s]] = pb[s];
            }
            __syncthreads();
            buf = nb;
        }
    }

    // Epilogue: scatter to [b, h, n, d]
    #pragma unroll
    for (int i = 0; i < 8; i++) {
        int row = bm + tr + i;
        int b_ = row >> 11;
        int n_ = row & 2047;
        #pragma unroll
        for (int j = 0; j < 8; j++) {
            int col = bn + tc + j;
            int h_ = col >> 6;
            int d_ = col & 63;
            out[(((size_t)(b_ * HH + h_) * NN) + n_) * HD + d_] = acc[i][j];
        }
    }
}

// ---------------------------------------------------------------------------
// Final SGEMM: d_out = g_ctx @ Wo + bo  (same pipelined structure)
// ---------------------------------------------------------------------------
__global__ __launch_bounds__(256) void out_gemm(
    const float* __restrict__ Wo,
    const float* __restrict__ bo,
    float* __restrict__ out)
{
    __shared__ float As[2][16][128];
    __shared__ float Bs[2][16][128];

    const int tid = threadIdx.x;
    const int bm = blockIdx.y * 128;
    const int bn = blockIdx.x * 128;
    const int tr = (tid >> 4) << 3;
    const int tc = (tid & 15) << 3;

    int a_r[2], a_c[2], b_r[2], b_c[2];
    #pragma unroll
    for (int s = 0; s < 2; s++) {
        int slot = tid + s * 256;
        a_r[s] = slot >> 2;
        a_c[s] = (slot & 3) << 2;
        b_r[s] = slot >> 5;
        b_c[s] = (slot & 31) << 2;
    }

    float acc[8][8];
    #pragma unroll
    for (int i = 0; i < 8; i++)
        #pragma unroll
        for (int j = 0; j < 8; j++) acc[i][j] = 0.f;

    #pragma unroll
    for (int s = 0; s < 2; s++) {
        float4 va = *(const float4*)&g_ctx[(size_t)(bm + a_r[s]) * DOUT + a_c[s]];
        As[0][a_c[s] + 0][a_r[s]] = va.x; As[0][a_c[s] + 1][a_r[s]] = va.y;
        As[0][a_c[s] + 2][a_r[s]] = va.z; As[0][a_c[s] + 3][a_r[s]] = va.w;
        *(float4*)&Bs[0][b_r[s]][b_c[s]] =
            *(const float4*)&Wo[(size_t)b_r[s] * DOUT + bn + b_c[s]];
    }
    __syncthreads();

    int buf = 0;
    const int NKT = DOUT / 16;
    for (int kt = 0; kt < NKT; kt++) {
        float4 pa[2], pb[2];
        if (kt < NKT - 1) {
            int k0n = (kt + 1) * 16;
            #pragma unroll
            for (int s = 0; s < 2; s++) {
                pa[s] = *(const float4*)&g_ctx[(size_t)(bm + a_r[s]) * DOUT + k0n + a_c[s]];
                pb[s] = *(const float4*)&Wo[(size_t)(k0n + b_r[s]) * DOUT + bn + b_c[s]];
            }
        }

        #pragma unroll
        for (int k = 0; k < 16; k++) {
            float a[8], b[8];
            #pragma unroll
            for (int i = 0; i < 8; i++) a[i] = As[buf][k][tr + i];
            #pragma unroll
            for (int j = 0; j < 8; j++) b[j] = Bs[buf][k][tc + j];
            #pragma unroll
            for (int i = 0; i < 8; i++)
                #pragma unroll
                for (int j = 0; j < 8; j++) acc[i][j] += a[i] * b[j];
        }

        if (kt < NKT - 1) {
            int nb = buf ^ 1;
            #pragma unroll
            for (int s = 0; s < 2; s++) {
                As[nb][a_c[s] + 0][a_r[s]] = pa[s].x;
                As[nb][a_c[s] + 1][a_r[s]] = pa[s].y;
                As[nb][a_c[s] + 2][a_r[s]] = pa[s].z;
                As[nb][a_c[s] + 3][a_r[s]] = pa[s].w;
                *(float4*)&Bs[nb][b_r[s]][b_c[s]] = pb[s];
            }
            __syncthreads();
            buf = nb;
        }
    }

    #pragma unroll
    for (int i = 0; i < 8; i++) {
        int row = bm + tr + i;
        #pragma unroll
        for (int j = 0; j < 8; j += 4) {
            int col = bn + tc + j;
            float4 bv = *(const float4*)&bo[col];
            float4 t;
            t.x = acc[i][j + 0] + bv.x;
            t.y = acc[i][j + 1] + bv.y;
            t.z = acc[i][j + 2] + bv.z;
            t.w = acc[i][j + 3] + bv.w;
            *(float4*)&out[(size_t)row * DOUT + col] = t;
        }
    }
}

// ---------------------------------------------------------------------------
// Attention: one thread per q-row.
// MUFU reduction: R_hat gate precomputed per-block into SMEM table (depends
// only on head + distance), softmax done WITHOUT max-tracking (logits are
// relu(..)*R_hat/8: non-negative and far below exp overflow for these
// magnitudes), masked positions contribute p=0 with no exp call.
// ---------------------------------------------------------------------------
__global__ __launch_bounds__(128) void attn_kernel(
    const float* __restrict__ wp,
    const float* __restrict__ vp)
{
    const int qb  = blockIdx.x;   // 0..15
    const int h   = blockIdx.y;   // 0..15
    const int b   = blockIdx.z;   // 0..1
    const int tid = threadIdx.x;
    const int r   = qb * 128 + tid;

    const size_t head_off = (size_t)(b * HH + h) * NN * HD;
    const float* qbase = g_q + head_off;
    const float* kbase = g_k + head_off;
    const float* vbase = g_v + head_off;

    const float wh = wp[h];
    const float vh = vp[h];
    const float c1 = 1.f + __expf(vh);

    __shared__ float Ks[32][64];
    __shared__ float Vs[32][64];
    __shared__ float Rs[NN];      // R_hat gate per distance (8KB)

    // Fill gate table: Rs[R] = (1+e^v) / (1+e^(v-w*R)), scaled by 1/sqrt(hd)
    for (int i = tid; i < NN; i += 128) {
        Rs[i] = c1 / (1.f + __expf(vh - wh * (float)i)) * 0.125f;
    }

    float qreg[64];
    #pragma unroll
    for (int i = 0; i < 16; i++) {
        float4 t = *(const float4*)&qbase[(size_t)r * HD + i * 4];
        qreg[i * 4 + 0] = t.x; qreg[i * 4 + 1] = t.y;
        qreg[i * 4 + 2] = t.z; qreg[i * 4 + 3] = t.w;
    }

    float acc[64];
    #pragma unroll
    for (int d = 0; d < 64; d++) acc[d] = 0.f;
    float lsum = 0.f;

    const int ktiles = (qb + 1) * 4;

    for (int kt = 0; kt < ktiles; kt++) {
        const int k0 = kt * 32;
        #pragma unroll
        for (int s = 0; s < 4; s++) {
            int slot = tid + s * 128;
            int rr  = slot >> 4;
            int c4  = (slot & 15) << 2;
            *(float4*)&Ks[rr][c4] = *(const float4*)&kbase[(size_t)(k0 + rr) * HD + c4];
            *(float4*)&Vs[rr][c4] = *(const float4*)&vbase[(size_t)(k0 + rr) * HD + c4];
        }
        __syncthreads();

        #pragma unroll
        for (int j = 0; j < 32; j++) {
            const int kidx = k0 + j;
            float s = 0.f;
            #pragma unroll
            for (int d = 0; d < 64; d++) s += qreg[d] * Ks[j][d];
            s = fmaxf(s, 0.f);
            int R = r - kidx;
            float logit = s * Rs[R < 0 ? 0 : R];
            float p = (R >= 0) ? __expf(logit) : 0.f;
            lsum += p;
            #pragma unroll
            for (int d = 0; d < 64; d++) acc[d] += p * Vs[j][d];
        }
        __syncthreads();
    }

    const float inv = 1.f / lsum;
    float* outp = g_ctx + ((size_t)(b * NN + r) * DOUT) + h * HD;
    #pragma unroll
    for (int i = 0; i < 16; i++) {
        float4 t;
        t.x = acc[i * 4 + 0] * inv;
        t.y = acc[i * 4 + 1] * inv;
        t.z = acc[i * 4 + 2] * inv;
        t.w = acc[i * 4 + 3] * inv;
        *(float4*)&outp[i * 4] = t;
    }
}

// ---------------------------------------------------------------------------
extern "C" void kernel_launch(void* const* d_in, const int* in_sizes, int n_in,
                              void* d_out, int out_size)
{
    const float* x  = (const float*)d_in[0];
    const float* Wq = (const float*)d_in[1];
    const float* Wk = (const float*)d_in[2];
    const float* Wv = (const float*)d_in[3];
    const float* Wo = (const float*)d_in[4];
    const float* bo = (const float*)d_in[5];
    const float* w  = (const float*)d_in[6];
    const float* v  = (const float*)d_in[7];
    float* out = (float*)d_out;

    dim3 g1(DOUT / 128, (BB * NN) / 128, 3);
    qkv_gemm<<<g1, 256>>>(x, Wq, Wk, Wv);

    dim3 g2(NN / 128, HH, BB);
    attn_kernel<<<g2, 128>>>(w, v);

    dim3 g3(DOUT / 128, (BB * NN) / 128, 1);
    out_gemm<<<g3, 256>>>(Wo, bo, out);
}

// round 6
// speedup vs baseline: 1.3679x; 1.3537x over previous
#include <cuda_runtime.h>

#define BB 2
#define NN 2048
#define DIN 1024
#define DOUT 1024
#define HH 16
#define HD 64

// Scratch (static device allocations — allowed)
__device__ float g_q[BB*HH*NN*HD];
__device__ float g_k[BB*HH*NN*HD];
__device__ float g_v[BB*HH*NN*HD];
__device__ float g_ctx[BB*NN*DOUT];

__device__ __forceinline__ unsigned f2tf32(float f) {
    unsigned r;
    asm("cvt.rna.tf32.f32 %0, %1;" : "=r"(r) : "f"(f));
    return r;
}

__device__ __forceinline__ void mma_tf32(float c[4],
    unsigned a0, unsigned a1, unsigned a2, unsigned a3,
    unsigned b0, unsigned b1)
{
    asm volatile(
        "mma.sync.aligned.m16n8k8.row.col.f32.tf32.tf32.f32 "
        "{%0,%1,%2,%3}, {%4,%5,%6,%7}, {%8,%9}, {%0,%1,%2,%3};"
        : "+f"(c[0]), "+f"(c[1]), "+f"(c[2]), "+f"(c[3])
        : "r"(a0), "r"(a1), "r"(a2), "r"(a3), "r"(b0), "r"(b1));
}

// ---------------------------------------------------------------------------
// Fused QKV GEMM on tensor cores (tf32 mma.sync.m16n8k8).
// C = x @ W{q,k,v}, scattered into [b,h,n,d] layout.
// Block: 128x128 tile, ktile=32, 256 threads = 8 warps in 2(m) x 4(n),
// each warp owns a 64x32 tile = 4x4 mma tiles (m16n8), 64 fp32 accum regs.
// SMEM: As[128][36] (pitch 36 -> conflict-free A-frag reads),
//       Bs[32][136]  (pitch 136 -> conflict-free B-frag reads).
// ---------------------------------------------------------------------------
__global__ __launch_bounds__(256) void qkv_gemm_tc(
    const float* __restrict__ x,
    const float* __restrict__ Wq,
    const float* __restrict__ Wk,
    const float* __restrict__ Wv)
{
    const float* W = (blockIdx.z == 0) ? Wq : (blockIdx.z == 1 ? Wk : Wv);
    float* out = (blockIdx.z == 0) ? g_q : (blockIdx.z == 1 ? g_k : g_v);

    __shared__ float As[128][36];
    __shared__ float Bs[32][136];

    const int tid  = threadIdx.x;
    const int warp = tid >> 5;
    const int lane = tid & 31;
    const int g    = lane >> 2;     // groupID (0..7)
    const int tg   = lane & 3;      // thread-in-group (0..3)
    const int wm   = (warp >> 2) * 64;   // 0, 64
    const int wn   = (warp & 3) * 32;    // 0, 32, 64, 96
    const int bm   = blockIdx.y * 128;
    const int bn   = blockIdx.x * 128;

    float c[16][4];
    #pragma unroll
    for (int t = 0; t < 16; t++)
        #pragma unroll
        for (int i = 0; i < 4; i++) c[t][i] = 0.f;

    for (int k0 = 0; k0 < DIN; k0 += 32) {
        // Load A tile 128x32 (4 float4 per thread)
        #pragma unroll
        for (int s = 0; s < 4; s++) {
            int slot = tid + s * 256;            // 0..1023
            int r  = slot >> 3;                  // 0..127
            int c4 = (slot & 7) << 2;            // 0..28
            *(float4*)&As[r][c4] =
                *(const float4*)&x[(size_t)(bm + r) * DIN + k0 + c4];
        }
        // Load B tile 32x128
        #pragma unroll
        for (int s = 0; s < 4; s++) {
            int slot = tid + s * 256;
            int r  = slot >> 5;                  // 0..31
            int c4 = (slot & 31) << 2;           // 0..124
            *(float4*)&Bs[r][c4] =
                *(const float4*)&W[(size_t)(k0 + r) * DOUT + bn + c4];
        }
        __syncthreads();

        #pragma unroll
        for (int kk = 0; kk < 32; kk += 8) {
            unsigned a[4][4], b[4][2];
            #pragma unroll
            for (int mt = 0; mt < 4; mt++) {
                int row = wm + mt * 16 + g;
                a[mt][0] = f2tf32(As[row    ][kk + tg    ]);
                a[mt][1] = f2tf32(As[row + 8][kk + tg    ]);
                a[mt][2] = f2tf32(As[row    ][kk + tg + 4]);
                a[mt][3] = f2tf32(As[row + 8][kk + tg + 4]);
            }
            #pragma unroll
            for (int nt = 0; nt < 4; nt++) {
                int col = wn + nt * 8 + g;
                b[nt][0] = f2tf32(Bs[kk + tg    ][col]);
                b[nt][1] = f2tf32(Bs[kk + tg + 4][col]);
            }
            #pragma unroll
            for (int mt = 0; mt < 4; mt++)
                #pragma unroll
                for (int nt = 0; nt < 4; nt++)
                    mma_tf32(c[mt * 4 + nt],
                             a[mt][0], a[mt][1], a[mt][2], a[mt][3],
                             b[nt][0], b[nt][1]);
        }
        __syncthreads();
    }

    // Epilogue: scatter to [b, h, n, d]
    #pragma unroll
    for (int mt = 0; mt < 4; mt++) {
        #pragma unroll
        for (int nt = 0; nt < 4; nt++) {
            int col = bn + wn + nt * 8 + tg * 2;
            int h_ = col >> 6;
            int d_ = col & 63;
            #pragma unroll
            for (int half = 0; half < 2; half++) {
                int row = bm + wm + mt * 16 + g + half * 8;
                int b_ = row >> 11;
                int n_ = row & 2047;
                float* p = &out[(((size_t)(b_ * HH + h_) * NN) + n_) * HD + d_];
                p[0] = c[mt * 4 + nt][half * 2 + 0];
                p[1] = c[mt * 4 + nt][half * 2 + 1];
            }
        }
    }
}

// ---------------------------------------------------------------------------
// Final SGEMM (exact fp32, single-buffered): d_out = g_ctx @ Wo + bo
// ---------------------------------------------------------------------------
__global__ __launch_bounds__(256) void out_gemm(
    const float* __restrict__ Wo,
    const float* __restrict__ bo,
    float* __restrict__ out)
{
    __shared__ float As[16][128];
    __shared__ float Bs[16][128];

    const int tid = threadIdx.x;
    const int bm = blockIdx.y * 128;
    const int bn = blockIdx.x * 128;
    const int tr = (tid >> 4) << 3;
    const int tc = (tid & 15) << 3;

    float acc[8][8];
    #pragma unroll
    for (int i = 0; i < 8; i++)
        #pragma unroll
        for (int j = 0; j < 8; j++) acc[i][j] = 0.f;

    for (int k0 = 0; k0 < DOUT; k0 += 16) {
        #pragma unroll
        for (int s = 0; s < 2; s++) {
            int slot = tid + s * 256;
            int r  = slot >> 2;
            int c4 = (slot & 3) << 2;
            float4 v = *(const float4*)&g_ctx[(size_t)(bm + r) * DOUT + k0 + c4];
            As[c4 + 0][r] = v.x; As[c4 + 1][r] = v.y;
            As[c4 + 2][r] = v.z; As[c4 + 3][r] = v.w;
        }
        #pragma unroll
        for (int s = 0; s < 2; s++) {
            int slot = tid + s * 256;
            int r  = slot >> 5;
            int c4 = (slot & 31) << 2;
            *(float4*)&Bs[r][c4] = *(const float4*)&Wo[(size_t)(k0 + r) * DOUT + bn + c4];
        }
        __syncthreads();

        #pragma unroll
        for (int k = 0; k < 16; k++) {
            float a[8], b[8];
            #pragma unroll
            for (int i = 0; i < 8; i++) a[i] = As[k][tr + i];
            #pragma unroll
            for (int j = 0; j < 8; j++) b[j] = Bs[k][tc + j];
            #pragma unroll
            for (int i = 0; i < 8; i++)
                #pragma unroll
                for (int j = 0; j < 8; j++) acc[i][j] += a[i] * b[j];
        }
        __syncthreads();
    }

    #pragma unroll
    for (int i = 0; i < 8; i++) {
        int row = bm + tr + i;
        #pragma unroll
        for (int j = 0; j < 8; j += 4) {
            int col = bn + tc + j;
            float4 bv = *(const float4*)&bo[col];
            float4 t;
            t.x = acc[i][j + 0] + bv.x;
            t.y = acc[i][j + 1] + bv.y;
            t.z = acc[i][j + 2] + bv.z;
            t.w = acc[i][j + 3] + bv.w;
            *(float4*)&out[(size_t)row * DOUT + col] = t;
        }
    }
}

// ---------------------------------------------------------------------------
// Attention: one thread per q-row (unchanged from R4; MMA rewrite next round).
// ---------------------------------------------------------------------------
__global__ __launch_bounds__(128) void attn_kernel(
    const float* __restrict__ wp,
    const float* __restrict__ vp)
{
    const int qb  = blockIdx.x;
    const int h   = blockIdx.y;
    const int b   = blockIdx.z;
    const int tid = threadIdx.x;
    const int r   = qb * 128 + tid;

    const size_t head_off = (size_t)(b * HH + h) * NN * HD;
    const float* qbase = g_q + head_off;
    const float* kbase = g_k + head_off;
    const float* vbase = g_v + head_off;

    const float wh = wp[h];
    const float vh = vp[h];
    const float c1 = 1.f + __expf(vh);

    __shared__ float Ks[32][64];
    __shared__ float Vs[32][64];
    __shared__ float Rs[NN];

    for (int i = tid; i < NN; i += 128) {
        Rs[i] = c1 / (1.f + __expf(vh - wh * (float)i)) * 0.125f;
    }

    float qreg[64];
    #pragma unroll
    for (int i = 0; i < 16; i++) {
        float4 t = *(const float4*)&qbase[(size_t)r * HD + i * 4];
        qreg[i * 4 + 0] = t.x; qreg[i * 4 + 1] = t.y;
        qreg[i * 4 + 2] = t.z; qreg[i * 4 + 3] = t.w;
    }

    float acc[64];
    #pragma unroll
    for (int d = 0; d < 64; d++) acc[d] = 0.f;
    float lsum = 0.f;

    const int ktiles = (qb + 1) * 4;

    for (int kt = 0; kt < ktiles; kt++) {
        const int k0 = kt * 32;
        #pragma unroll
        for (int s = 0; s < 4; s++) {
            int slot = tid + s * 128;
            int rr  = slot >> 4;
            int c4  = (slot & 15) << 2;
            *(float4*)&Ks[rr][c4] = *(const float4*)&kbase[(size_t)(k0 + rr) * HD + c4];
            *(float4*)&Vs[rr][c4] = *(const float4*)&vbase[(size_t)(k0 + rr) * HD + c4];
        }
        __syncthreads();

        #pragma unroll
        for (int j = 0; j < 32; j++) {
            const int kidx = k0 + j;
            float s = 0.f;
            #pragma unroll
            for (int d = 0; d < 64; d++) s += qreg[d] * Ks[j][d];
            s = fmaxf(s, 0.f);
            int R = r - kidx;
            float logit = s * Rs[R < 0 ? 0 : R];
            float p = (R >= 0) ? __expf(logit) : 0.f;
            lsum += p;
            #pragma unroll
            for (int d = 0; d < 64; d++) acc[d] += p * Vs[j][d];
        }
        __syncthreads();
    }

    const float inv = 1.f / lsum;
    float* outp = g_ctx + ((size_t)(b * NN + r) * DOUT) + h * HD;
    #pragma unroll
    for (int i = 0; i < 16; i++) {
        float4 t;
        t.x = acc[i * 4 + 0] * inv;
        t.y = acc[i * 4 + 1] * inv;
        t.z = acc[i * 4 + 2] * inv;
        t.w = acc[i * 4 + 3] * inv;
        *(float4*)&outp[i * 4] = t;
    }
}

// ---------------------------------------------------------------------------
extern "C" void kernel_launch(void* const* d_in, const int* in_sizes, int n_in,
                              void* d_out, int out_size)
{
    const float* x  = (const float*)d_in[0];
    const float* Wq = (const float*)d_in[1];
    const float* Wk = (const float*)d_in[2];
    const float* Wv = (const float*)d_in[3];
    const float* Wo = (const float*)d_in[4];
    const float* bo = (const float*)d_in[5];
    const float* w  = (const float*)d_in[6];
    const float* v  = (const float*)d_in[7];
    float* out = (float*)d_out;

    dim3 g1(DOUT / 128, (BB * NN) / 128, 3);
    qkv_gemm_tc<<<g1, 256>>>(x, Wq, Wk, Wv);

    dim3 g2(NN / 128, HH, BB);
    attn_kernel<<<g2, 128>>>(w, v);

    dim3 g3(DOUT / 128, (BB * NN) / 128, 1);
    out_gemm<<<g3, 256>>>(Wo, bo, out);
}

// round 8
// speedup vs baseline: 2.6663x; 1.9492x over previous
#include <cuda_runtime.h>

#define BB 2
#define NN 2048
#define DIN 1024
#define DOUT 1024
#define HH 16
#define HD 64

// Scratch (static device allocations — allowed)
__device__ float g_q[BB*HH*NN*HD];
__device__ float g_k[BB*HH*NN*HD];
__device__ float g_v[BB*HH*NN*HD];
__device__ float g_ctx[BB*NN*DOUT];

__device__ __forceinline__ unsigned f2tf32(float f) {
    unsigned r;
    asm("cvt.rna.tf32.f32 %0, %1;" : "=r"(r) : "f"(f));
    return r;
}

__device__ __forceinline__ void mma_tf32(float c[4],
    unsigned a0, unsigned a1, unsigned a2, unsigned a3,
    unsigned b0, unsigned b1)
{
    asm volatile(
        "mma.sync.aligned.m16n8k8.row.col.f32.tf32.tf32.f32 "
        "{%0,%1,%2,%3}, {%4,%5,%6,%7}, {%8,%9}, {%0,%1,%2,%3};"
        : "+f"(c[0]), "+f"(c[1]), "+f"(c[2]), "+f"(c[3])
        : "r"(a0), "r"(a1), "r"(a2), "r"(a3), "r"(b0), "r"(b1));
}

// ---------------------------------------------------------------------------
// Fused QKV GEMM on tensor cores (tf32 mma.sync.m16n8k8). Unchanged from R5.
// ---------------------------------------------------------------------------
__global__ __launch_bounds__(256) void qkv_gemm_tc(
    const float* __restrict__ x,
    const float* __restrict__ Wq,
    const float* __restrict__ Wk,
    const float* __restrict__ Wv)
{
    const float* W = (blockIdx.z == 0) ? Wq : (blockIdx.z == 1 ? Wk : Wv);
    float* out = (blockIdx.z == 0) ? g_q : (blockIdx.z == 1 ? g_k : g_v);

    __shared__ float As[128][36];
    __shared__ float Bs[32][136];

    const int tid  = threadIdx.x;
    const int warp = tid >> 5;
    const int lane = tid & 31;
    const int g    = lane >> 2;
    const int tg   = lane & 3;
    const int wm   = (warp >> 2) * 64;
    const int wn   = (warp & 3) * 32;
    const int bm   = blockIdx.y * 128;
    const int bn   = blockIdx.x * 128;

    float c[16][4];
    #pragma unroll
    for (int t = 0; t < 16; t++)
        #pragma unroll
        for (int i = 0; i < 4; i++) c[t][i] = 0.f;

    for (int k0 = 0; k0 < DIN; k0 += 32) {
        #pragma unroll
        for (int s = 0; s < 4; s++) {
            int slot = tid + s * 256;
            int r  = slot >> 3;
            int c4 = (slot & 7) << 2;
            *(float4*)&As[r][c4] =
                *(const float4*)&x[(size_t)(bm + r) * DIN + k0 + c4];
        }
        #pragma unroll
        for (int s = 0; s < 4; s++) {
            int slot = tid + s * 256;
            int r  = slot >> 5;
            int c4 = (slot & 31) << 2;
            *(float4*)&Bs[r][c4] =
                *(const float4*)&W[(size_t)(k0 + r) * DOUT + bn + c4];
        }
        __syncthreads();

        #pragma unroll
        for (int kk = 0; kk < 32; kk += 8) {
            unsigned a[4][4], b[4][2];
            #pragma unroll
            for (int mt = 0; mt < 4; mt++) {
                int row = wm + mt * 16 + g;
                a[mt][0] = f2tf32(As[row    ][kk + tg    ]);
                a[mt][1] = f2tf32(As[row + 8][kk + tg    ]);
                a[mt][2] = f2tf32(As[row    ][kk + tg + 4]);
                a[mt][3] = f2tf32(As[row + 8][kk + tg + 4]);
            }
            #pragma unroll
            for (int nt = 0; nt < 4; nt++) {
                int col = wn + nt * 8 + g;
                b[nt][0] = f2tf32(Bs[kk + tg    ][col]);
                b[nt][1] = f2tf32(Bs[kk + tg + 4][col]);
            }
            #pragma unroll
            for (int mt = 0; mt < 4; mt++)
                #pragma unroll
                for (int nt = 0; nt < 4; nt++)
                    mma_tf32(c[mt * 4 + nt],
                             a[mt][0], a[mt][1], a[mt][2], a[mt][3],
                             b[nt][0], b[nt][1]);
        }
        __syncthreads();
    }

    #pragma unroll
    for (int mt = 0; mt < 4; mt++) {
        #pragma unroll
        for (int nt = 0; nt < 4; nt++) {
            int col = bn + wn + nt * 8 + tg * 2;
            int h_ = col >> 6;
            int d_ = col & 63;
            #pragma unroll
            for (int half = 0; half < 2; half++) {
                int row = bm + wm + mt * 16 + g + half * 8;
                int b_ = row >> 11;
                int n_ = row & 2047;
                float* p = &out[(((size_t)(b_ * HH + h_) * NN) + n_) * HD + d_];
                p[0] = c[mt * 4 + nt][half * 2 + 0];
                p[1] = c[mt * 4 + nt][half * 2 + 1];
            }
        }
    }
}

// ---------------------------------------------------------------------------
// Final SGEMM (exact fp32): d_out = g_ctx @ Wo + bo. Unchanged.
// ---------------------------------------------------------------------------
__global__ __launch_bounds__(256) void out_gemm(
    const float* __restrict__ Wo,
    const float* __restrict__ bo,
    float* __restrict__ out)
{
    __shared__ float As[16][128];
    __shared__ float Bs[16][128];

    const int tid = threadIdx.x;
    const int bm = blockIdx.y * 128;
    const int bn = blockIdx.x * 128;
    const int tr = (tid >> 4) << 3;
    const int tc = (tid & 15) << 3;

    float acc[8][8];
    #pragma unroll
    for (int i = 0; i < 8; i++)
        #pragma unroll
        for (int j = 0; j < 8; j++) acc[i][j] = 0.f;

    for (int k0 = 0; k0 < DOUT; k0 += 16) {
        #pragma unroll
        for (int s = 0; s < 2; s++) {
            int slot = tid + s * 256;
            int r  = slot >> 2;
            int c4 = (slot & 3) << 2;
            float4 v = *(const float4*)&g_ctx[(size_t)(bm + r) * DOUT + k0 + c4];
            As[c4 + 0][r] = v.x; As[c4 + 1][r] = v.y;
            As[c4 + 2][r] = v.z; As[c4 + 3][r] = v.w;
        }
        #pragma unroll
        for (int s = 0; s < 2; s++) {
            int slot = tid + s * 256;
            int r  = slot >> 5;
            int c4 = (slot & 31) << 2;
            *(float4*)&Bs[r][c4] = *(const float4*)&Wo[(size_t)(k0 + r) * DOUT + bn + c4];
        }
        __syncthreads();

        #pragma unroll
        for (int k = 0; k < 16; k++) {
            float a[8], b[8];
            #pragma unroll
            for (int i = 0; i < 8; i++) a[i] = As[k][tr + i];
            #pragma unroll
            for (int j = 0; j < 8; j++) b[j] = Bs[k][tc + j];
            #pragma unroll
            for (int i = 0; i < 8; i++)
                #pragma unroll
                for (int j = 0; j < 8; j++) acc[i][j] += a[i] * b[j];
        }
        __syncthreads();
    }

    #pragma unroll
    for (int i = 0; i < 8; i++) {
        int row = bm + tr + i;
        #pragma unroll
        for (int j = 0; j < 8; j += 4) {
            int col = bn + tc + j;
            float4 bv = *(const float4*)&bo[col];
            float4 t;
            t.x = acc[i][j + 0] + bv.x;
            t.y = acc[i][j + 1] + bv.y;
            t.z = acc[i][j + 2] + bv.z;
            t.w = acc[i][j + 3] + bv.w;
            *(float4*)&out[(size_t)row * DOUT + col] = t;
        }
    }
}

// ---------------------------------------------------------------------------
// Tensor-core flash attention (R6 structure, K-fragment read FIXED: for
// S = Q K^T the reduction dim is d, so B[k=d][n=key] = Ks[key][d] must be
// read as Ks[col*68 + kk+tg], not Ks[(kk+tg)*68 + col]).
// ---------------------------------------------------------------------------
#define QS_OFF 0
#define KS_OFF (128*68)
#define VS_OFF (KS_OFF + 64*68)
#define PS_OFF (VS_OFF + 64*68)
#define RS_OFF (PS_OFF + 128*68)
#define LS_OFF (RS_OFF + 2048)
#define ATTN_SMEM_FLOATS (LS_OFF + 128)
#define ATTN_SMEM_BYTES (ATTN_SMEM_FLOATS * 4)

__global__ __launch_bounds__(256) void attn_tc(
    const float* __restrict__ wp,
    const float* __restrict__ vp)
{
    extern __shared__ float sm[];
    float* Qs = sm + QS_OFF;
    float* Ks = sm + KS_OFF;
    float* Vs = sm + VS_OFF;
    float* Ps = sm + PS_OFF;
    float* Rs = sm + RS_OFF;
    float* Ls = sm + LS_OFF;

    const int qb  = blockIdx.x;
    const int h   = blockIdx.y;
    const int b   = blockIdx.z;
    const int tid = threadIdx.x;
    const int warp = tid >> 5;
    const int lane = tid & 31;
    const int g  = lane >> 2;
    const int tg = lane & 3;
    const int wm = (warp >> 1) * 32;   // 0,32,64,96
    const int wn = (warp & 1) * 32;    // 0,32

    const size_t head_off = (size_t)(b * HH + h) * NN * HD;
    const float* qbase = g_q + head_off;
    const float* kbase = g_k + head_off;
    const float* vbase = g_v + head_off;

    const float wh = wp[h];
    const float vh = vp[h];
    const float c1 = 1.f + __expf(vh);

    for (int i = tid; i < NN; i += 256)
        Rs[i] = c1 / (1.f + __expf(vh - wh * (float)i)) * 0.125f;
    if (tid < 128) Ls[tid] = 0.f;

    #pragma unroll
    for (int s = 0; s < 8; s++) {
        int slot = tid + s * 256;
        int r  = slot >> 4;
        int c4 = (slot & 15) << 2;
        *(float4*)&Qs[r * 68 + c4] =
            *(const float4*)&qbase[(size_t)(qb * 128 + r) * HD + c4];
    }
    __syncthreads();

    float co[2][4][4];
    #pragma unroll
    for (int mt = 0; mt < 2; mt++)
        #pragma unroll
        for (int nt = 0; nt < 4; nt++)
            #pragma unroll
            for (int i = 0; i < 4; i++) co[mt][nt][i] = 0.f;

    const int ktmax = (qb + 1) * 2;
    for (int kt = 0; kt < ktmax; kt++) {
        const int k0 = kt * 64;

        #pragma unroll
        for (int s = 0; s < 4; s++) {
            int slot = tid + s * 256;
            int r  = slot >> 4;
            int c4 = (slot & 15) << 2;
            *(float4*)&Ks[r * 68 + c4] =
                *(const float4*)&kbase[(size_t)(k0 + r) * HD + c4];
            *(float4*)&Vs[r * 68 + c4] =
                *(const float4*)&vbase[(size_t)(k0 + r) * HD + c4];
        }
        __syncthreads();

        // ---- S = Q K^T (Q hi/lo split; B fragment = Ks transposed read) ----
        float cs[2][4][4];
        #pragma unroll
        for (int mt = 0; mt < 2; mt++)
            #pragma unroll
            for (int nt = 0; nt < 4; nt++)
                #pragma unroll
                for (int i = 0; i < 4; i++) cs[mt][nt][i] = 0.f;

        #pragma unroll
        for (int kk = 0; kk < 64; kk += 8) {
            unsigned ahi[2][4], alo[2][4], bb[4][2];
            #pragma unroll
            for (int mt = 0; mt < 2; mt++) {
                int row = wm + mt * 16 + g;
                float q0 = Qs[row * 68 + kk + tg];
                float q1 = Qs[(row + 8) * 68 + kk + tg];
                float q2 = Qs[row * 68 + kk + tg + 4];
                float q3 = Qs[(row + 8) * 68 + kk + tg + 4];
                ahi[mt][0] = f2tf32(q0); ahi[mt][1] = f2tf32(q1);
                ahi[mt][2] = f2tf32(q2); ahi[mt][3] = f2tf32(q3);
                alo[mt][0] = f2tf32(q0 - __uint_as_float(ahi[mt][0]));
                alo[mt][1] = f2tf32(q1 - __uint_as_float(ahi[mt][1]));
                alo[mt][2] = f2tf32(q2 - __uint_as_float(ahi[mt][2]));
                alo[mt][3] = f2tf32(q3 - __uint_as_float(ahi[mt][3]));
            }
            #pragma unroll
            for (int nt = 0; nt < 4; nt++) {
                int col = wn + nt * 8 + g;   // key index within tile
                bb[nt][0] = f2tf32(Ks[col * 68 + kk + tg    ]);
                bb[nt][1] = f2tf32(Ks[col * 68 + kk + tg + 4]);
            }
            #pragma unroll
            for (int mt = 0; mt < 2; mt++)
                #pragma unroll
                for (int nt = 0; nt < 4; nt++) {
                    mma_tf32(cs[mt][nt],
                             ahi[mt][0], ahi[mt][1], ahi[mt][2], ahi[mt][3],
                             bb[nt][0], bb[nt][1]);
                    mma_tf32(cs[mt][nt],
                             alo[mt][0], alo[mt][1], alo[mt][2], alo[mt][3],
                             bb[nt][0], bb[nt][1]);
                }
        }

        // ---- elementwise: relu, gate, exp; P -> SMEM; row partial sums ----
        float rp[2][2] = {{0.f, 0.f}, {0.f, 0.f}};
        #pragma unroll
        for (int mt = 0; mt < 2; mt++) {
            #pragma unroll
            for (int nt = 0; nt < 4; nt++) {
                #pragma unroll
                for (int i = 0; i < 4; i++) {
                    int half = i >> 1;
                    int row_l = wm + mt * 16 + g + half * 8;
                    int col = wn + nt * 8 + tg * 2 + (i & 1);
                    int R = (qb * 128 + row_l) - (k0 + col);
                    float s = fmaxf(cs[mt][nt][i], 0.f);
                    float p = (R >= 0) ? __expf(s * Rs[R]) : 0.f;
                    Ps[row_l * 68 + col] = p;
                    rp[mt][half] += p;
                }
            }
        }
        #pragma unroll
        for (int mt = 0; mt < 2; mt++)
            #pragma unroll
            for (int half = 0; half < 2; half++) {
                float v = rp[mt][half];
                v += __shfl_xor_sync(0xffffffff, v, 1);
                v += __shfl_xor_sync(0xffffffff, v, 2);
                if (tg == 0)
                    atomicAdd(&Ls[wm + mt * 16 + g + half * 8], v);
            }
        __syncthreads();

        // ---- O += P V ----
        #pragma unroll
        for (int kk = 0; kk < 64; kk += 8) {
            unsigned pa[2][4], bb[4][2];
            #pragma unroll
            for (int mt = 0; mt < 2; mt++) {
                int row = wm + mt * 16 + g;
                pa[mt][0] = f2tf32(Ps[row * 68 + kk + tg]);
                pa[mt][1] = f2tf32(Ps[(row + 8) * 68 + kk + tg]);
                pa[mt][2] = f2tf32(Ps[row * 68 + kk + tg + 4]);
                pa[mt][3] = f2tf32(Ps[(row + 8) * 68 + kk + tg + 4]);
            }
            #pragma unroll
            for (int nt = 0; nt < 4; nt++) {
                int col = wn + nt * 8 + g;   // d index
                bb[nt][0] = f2tf32(Vs[(kk + tg) * 68 + col]);
                bb[nt][1] = f2tf32(Vs[(kk + tg + 4) * 68 + col]);
            }
            #pragma unroll
            for (int mt = 0; mt < 2; mt++)
                #pragma unroll
                for (int nt = 0; nt < 4; nt++)
                    mma_tf32(co[mt][nt],
                             pa[mt][0], pa[mt][1], pa[mt][2], pa[mt][3],
                             bb[nt][0], bb[nt][1]);
        }
        __syncthreads();
    }

    // ---- finalize: normalize and write ctx [b, n, h*64+d] ----
    #pragma unroll
    for (int mt = 0; mt < 2; mt++) {
        #pragma unroll
        for (int half = 0; half < 2; half++) {
            int row_l = wm + mt * 16 + g + half * 8;
            float inv = 1.f / Ls[row_l];
            int n_ = qb * 128 + row_l;
            float* op = g_ctx + ((size_t)(b * NN + n_) * DOUT) + h * HD;
            #pragma unroll
            for (int nt = 0; nt < 4; nt++) {
                int col = wn + nt * 8 + tg * 2;
                op[col]     = co[mt][nt][half * 2 + 0] * inv;
                op[col + 1] = co[mt][nt][half * 2 + 1] * inv;
            }
        }
    }
}

// ---------------------------------------------------------------------------
extern "C" void kernel_launch(void* const* d_in, const int* in_sizes, int n_in,
                              void* d_out, int out_size)
{
    const float* x  = (const float*)d_in[0];
    const float* Wq = (const float*)d_in[1];
    const float* Wk = (const float*)d_in[2];
    const float* Wv = (const float*)d_in[3];
    const float* Wo = (const float*)d_in[4];
    const float* bo = (const float*)d_in[5];
    const float* w  = (const float*)d_in[6];
    const float* v  = (const float*)d_in[7];
    float* out = (float*)d_out;

    cudaFuncSetAttribute(attn_tc,
        cudaFuncAttributeMaxDynamicSharedMemorySize, ATTN_SMEM_BYTES);

    dim3 g1(DOUT / 128, (BB * NN) / 128, 3);
    qkv_gemm_tc<<<g1, 256>>>(x, Wq, Wk, Wv);

    dim3 g2(NN / 128, HH, BB);
    attn_tc<<<g2, 256, ATTN_SMEM_BYTES>>>(w, v);

    dim3 g3(DOUT / 128, (BB * NN) / 128, 1);
    out_gemm<<<g3, 256>>>(Wo, bo, out);
}

// round 9
// speedup vs baseline: 2.9847x; 1.1194x over previous
#include <cuda_runtime.h>

#define BB 2
#define NN 2048
#define DIN 1024
#define DOUT 1024
#define HH 16
#define HD 64

// Scratch (static device allocations — allowed)
__device__ float g_q[BB*HH*NN*HD];
__device__ float g_k[BB*HH*NN*HD];
__device__ float g_v[BB*HH*NN*HD];
__device__ float g_ctx[BB*NN*DOUT];

__device__ __forceinline__ unsigned f2tf32(float f) {
    unsigned r;
    asm("cvt.rna.tf32.f32 %0, %1;" : "=r"(r) : "f"(f));
    return r;
}

__device__ __forceinline__ void mma_tf32(float c[4],
    unsigned a0, unsigned a1, unsigned a2, unsigned a3,
    unsigned b0, unsigned b1)
{
    asm volatile(
        "mma.sync.aligned.m16n8k8.row.col.f32.tf32.tf32.f32 "
        "{%0,%1,%2,%3}, {%4,%5,%6,%7}, {%8,%9}, {%0,%1,%2,%3};"
        : "+f"(c[0]), "+f"(c[1]), "+f"(c[2]), "+f"(c[3])
        : "r"(a0), "r"(a1), "r"(a2), "r"(a3), "r"(b0), "r"(b1));
}

// ---------------------------------------------------------------------------
// Fused QKV GEMM on tensor cores (tf32 mma.sync.m16n8k8). Unchanged.
// ---------------------------------------------------------------------------
__global__ __launch_bounds__(256) void qkv_gemm_tc(
    const float* __restrict__ x,
    const float* __restrict__ Wq,
    const float* __restrict__ Wk,
    const float* __restrict__ Wv)
{
    const float* W = (blockIdx.z == 0) ? Wq : (blockIdx.z == 1 ? Wk : Wv);
    float* out = (blockIdx.z == 0) ? g_q : (blockIdx.z == 1 ? g_k : g_v);

    __shared__ float As[128][36];
    __shared__ float Bs[32][136];

    const int tid  = threadIdx.x;
    const int warp = tid >> 5;
    const int lane = tid & 31;
    const int g    = lane >> 2;
    const int tg   = lane & 3;
    const int wm   = (warp >> 2) * 64;
    const int wn   = (warp & 3) * 32;
    const int bm   = blockIdx.y * 128;
    const int bn   = blockIdx.x * 128;

    float c[16][4];
    #pragma unroll
    for (int t = 0; t < 16; t++)
        #pragma unroll
        for (int i = 0; i < 4; i++) c[t][i] = 0.f;

    for (int k0 = 0; k0 < DIN; k0 += 32) {
        #pragma unroll
        for (int s = 0; s < 4; s++) {
            int slot = tid + s * 256;
            int r  = slot >> 3;
            int c4 = (slot & 7) << 2;
            *(float4*)&As[r][c4] =
                *(const float4*)&x[(size_t)(bm + r) * DIN + k0 + c4];
        }
        #pragma unroll
        for (int s = 0; s < 4; s++) {
            int slot = tid + s * 256;
            int r  = slot >> 5;
            int c4 = (slot & 31) << 2;
            *(float4*)&Bs[r][c4] =
                *(const float4*)&W[(size_t)(k0 + r) * DOUT + bn + c4];
        }
        __syncthreads();

        #pragma unroll
        for (int kk = 0; kk < 32; kk += 8) {
            unsigned a[4][4], b[4][2];
            #pragma unroll
            for (int mt = 0; mt < 4; mt++) {
                int row = wm + mt * 16 + g;
                a[mt][0] = f2tf32(As[row    ][kk + tg    ]);
                a[mt][1] = f2tf32(As[row + 8][kk + tg    ]);
                a[mt][2] = f2tf32(As[row    ][kk + tg + 4]);
                a[mt][3] = f2tf32(As[row + 8][kk + tg + 4]);
            }
            #pragma unroll
            for (int nt = 0; nt < 4; nt++) {
                int col = wn + nt * 8 + g;
                b[nt][0] = f2tf32(Bs[kk + tg    ][col]);
                b[nt][1] = f2tf32(Bs[kk + tg + 4][col]);
            }
            #pragma unroll
            for (int mt = 0; mt < 4; mt++)
                #pragma unroll
                for (int nt = 0; nt < 4; nt++)
                    mma_tf32(c[mt * 4 + nt],
                             a[mt][0], a[mt][1], a[mt][2], a[mt][3],
                             b[nt][0], b[nt][1]);
        }
        __syncthreads();
    }

    #pragma unroll
    for (int mt = 0; mt < 4; mt++) {
        #pragma unroll
        for (int nt = 0; nt < 4; nt++) {
            int col = bn + wn + nt * 8 + tg * 2;
            int h_ = col >> 6;
            int d_ = col & 63;
            #pragma unroll
            for (int half = 0; half < 2; half++) {
                int row = bm + wm + mt * 16 + g + half * 8;
                int b_ = row >> 11;
                int n_ = row & 2047;
                float* p = &out[(((size_t)(b_ * HH + h_) * NN) + n_) * HD + d_];
                p[0] = c[mt * 4 + nt][half * 2 + 0];
                p[1] = c[mt * 4 + nt][half * 2 + 1];
            }
        }
    }
}

// ---------------------------------------------------------------------------
// Output GEMM on tensor cores: d_out = g_ctx @ Wo + bo.
// Same fragment geometry as qkv_gemm_tc. Precision: A (ctx) hi/lo split
// (2 MMAs), B (Wo) single tf32 rounding -> added error ~= one tf32 rounding.
// ---------------------------------------------------------------------------
__global__ __launch_bounds__(256) void out_gemm_tc(
    const float* __restrict__ Wo,
    const float* __restrict__ bo,
    float* __restrict__ out)
{
    __shared__ float As[128][36];
    __shared__ float Bs[32][136];

    const int tid  = threadIdx.x;
    const int warp = tid >> 5;
    const int lane = tid & 31;
    const int g    = lane >> 2;
    const int tg   = lane & 3;
    const int wm   = (warp >> 2) * 64;
    const int wn   = (warp & 3) * 32;
    const int bm   = blockIdx.y * 128;
    const int bn   = blockIdx.x * 128;

    float c[16][4];
    #pragma unroll
    for (int t = 0; t < 16; t++)
        #pragma unroll
        for (int i = 0; i < 4; i++) c[t][i] = 0.f;

    for (int k0 = 0; k0 < DOUT; k0 += 32) {
        #pragma unroll
        for (int s = 0; s < 4; s++) {
            int slot = tid + s * 256;
            int r  = slot >> 3;
            int c4 = (slot & 7) << 2;
            *(float4*)&As[r][c4] =
                *(const float4*)&g_ctx[(size_t)(bm + r) * DOUT + k0 + c4];
        }
        #pragma unroll
        for (int s = 0; s < 4; s++) {
            int slot = tid + s * 256;
            int r  = slot >> 5;
            int c4 = (slot & 31) << 2;
            *(float4*)&Bs[r][c4] =
                *(const float4*)&Wo[(size_t)(k0 + r) * DOUT + bn + c4];
        }
        __syncthreads();

        #pragma unroll
        for (int kk = 0; kk < 32; kk += 8) {
            unsigned ahi[4][4], alo[4][4], b[4][2];
            #pragma unroll
            for (int mt = 0; mt < 4; mt++) {
                int row = wm + mt * 16 + g;
                float a0 = As[row    ][kk + tg    ];
                float a1 = As[row + 8][kk + tg    ];
                float a2 = As[row    ][kk + tg + 4];
                float a3 = As[row + 8][kk + tg + 4];
                ahi[mt][0] = f2tf32(a0); ahi[mt][1] = f2tf32(a1);
                ahi[mt][2] = f2tf32(a2); ahi[mt][3] = f2tf32(a3);
                alo[mt][0] = f2tf32(a0 - __uint_as_float(ahi[mt][0]));
                alo[mt][1] = f2tf32(a1 - __uint_as_float(ahi[mt][1]));
                alo[mt][2] = f2tf32(a2 - __uint_as_float(ahi[mt][2]));
                alo[mt][3] = f2tf32(a3 - __uint_as_float(ahi[mt][3]));
            }
            #pragma unroll
            for (int nt = 0; nt < 4; nt++) {
                int col = wn + nt * 8 + g;
                b[nt][0] = f2tf32(Bs[kk + tg    ][col]);
                b[nt][1] = f2tf32(Bs[kk + tg + 4][col]);
            }
            #pragma unroll
            for (int mt = 0; mt < 4; mt++)
                #pragma unroll
                for (int nt = 0; nt < 4; nt++) {
                    mma_tf32(c[mt * 4 + nt],
                             ahi[mt][0], ahi[mt][1], ahi[mt][2], ahi[mt][3],
                             b[nt][0], b[nt][1]);
                    mma_tf32(c[mt * 4 + nt],
                             alo[mt][0], alo[mt][1], alo[mt][2], alo[mt][3],
                             b[nt][0], b[nt][1]);
                }
        }
        __syncthreads();
    }

    #pragma unroll
    for (int mt = 0; mt < 4; mt++) {
        #pragma unroll
        for (int nt = 0; nt < 4; nt++) {
            int col = bn + wn + nt * 8 + tg * 2;
            float b0 = bo[col], b1 = bo[col + 1];
            #pragma unroll
            for (int half = 0; half < 2; half++) {
                int row = bm + wm + mt * 16 + g + half * 8;
                float* p = &out[(size_t)row * DOUT + col];
                p[0] = c[mt * 4 + nt][half * 2 + 0] + b0;
                p[1] = c[mt * 4 + nt][half * 2 + 1] + b1;
            }
        }
    }
}

// ---------------------------------------------------------------------------
// Tensor-core flash attention. Unchanged from R7 (correct).
// NOTE: the Ks fragment read MUST stay transposed (Ks[col*68 + kk+tg]) —
// for S = Q K^T the MMA reduction dim is d, keys are the n dim.
// ---------------------------------------------------------------------------
#define QS_OFF 0
#define KS_OFF (128*68)
#define VS_OFF (KS_OFF + 64*68)
#define PS_OFF (VS_OFF + 64*68)
#define RS_OFF (PS_OFF + 128*68)
#define LS_OFF (RS_OFF + 2048)
#define ATTN_SMEM_FLOATS (LS_OFF + 128)
#define ATTN_SMEM_BYTES (ATTN_SMEM_FLOATS * 4)

__global__ __launch_bounds__(256) void attn_tc(
    const float* __restrict__ wp,
    const float* __restrict__ vp)
{
    extern __shared__ float sm[];
    float* Qs = sm + QS_OFF;
    float* Ks = sm + KS_OFF;
    float* Vs = sm + VS_OFF;
    float* Ps = sm + PS_OFF;
    float* Rs = sm + RS_OFF;
    float* Ls = sm + LS_OFF;

    const int qb  = blockIdx.x;
    const int h   = blockIdx.y;
    const int b   = blockIdx.z;
    const int tid = threadIdx.x;
    const int warp = tid >> 5;
    const int lane = tid & 31;
    const int g  = lane >> 2;
    const int tg = lane & 3;
    const int wm = (warp >> 1) * 32;
    const int wn = (warp & 1) * 32;

    const size_t head_off = (size_t)(b * HH + h) * NN * HD;
    const float* qbase = g_q + head_off;
    const float* kbase = g_k + head_off;
    const float* vbase = g_v + head_off;

    const float wh = wp[h];
    const float vh = vp[h];
    const float c1 = 1.f + __expf(vh);

    for (int i = tid; i < NN; i += 256)
        Rs[i] = c1 / (1.f + __expf(vh - wh * (float)i)) * 0.125f;
    if (tid < 128) Ls[tid] = 0.f;

    #pragma unroll
    for (int s = 0; s < 8; s++) {
        int slot = tid + s * 256;
        int r  = slot >> 4;
        int c4 = (slot & 15) << 2;
        *(float4*)&Qs[r * 68 + c4] =
            *(const float4*)&qbase[(size_t)(qb * 128 + r) * HD + c4];
    }
    __syncthreads();

    float co[2][4][4];
    #pragma unroll
    for (int mt = 0; mt < 2; mt++)
        #pragma unroll
        for (int nt = 0; nt < 4; nt++)
            #pragma unroll
            for (int i = 0; i < 4; i++) co[mt][nt][i] = 0.f;

    const int ktmax = (qb + 1) * 2;
    for (int kt = 0; kt < ktmax; kt++) {
        const int k0 = kt * 64;

        #pragma unroll
        for (int s = 0; s < 4; s++) {
            int slot = tid + s * 256;
            int r  = slot >> 4;
            int c4 = (slot & 15) << 2;
            *(float4*)&Ks[r * 68 + c4] =
                *(const float4*)&kbase[(size_t)(k0 + r) * HD + c4];
            *(float4*)&Vs[r * 68 + c4] =
                *(const float4*)&vbase[(size_t)(k0 + r) * HD + c4];
        }
        __syncthreads();

        float cs[2][4][4];
        #pragma unroll
        for (int mt = 0; mt < 2; mt++)
            #pragma unroll
            for (int nt = 0; nt < 4; nt++)
                #pragma unroll
                for (int i = 0; i < 4; i++) cs[mt][nt][i] = 0.f;

        #pragma unroll
        for (int kk = 0; kk < 64; kk += 8) {
            unsigned ahi[2][4], alo[2][4], bb[4][2];
            #pragma unroll
            for (int mt = 0; mt < 2; mt++) {
                int row = wm + mt * 16 + g;
                float q0 = Qs[row * 68 + kk + tg];
                float q1 = Qs[(row + 8) * 68 + kk + tg];
                float q2 = Qs[row * 68 + kk + tg + 4];
                float q3 = Qs[(row + 8) * 68 + kk + tg + 4];
                ahi[mt][0] = f2tf32(q0); ahi[mt][1] = f2tf32(q1);
                ahi[mt][2] = f2tf32(q2); ahi[mt][3] = f2tf32(q3);
                alo[mt][0] = f2tf32(q0 - __uint_as_float(ahi[mt][0]));
                alo[mt][1] = f2tf32(q1 - __uint_as_float(ahi[mt][1]));
                alo[mt][2] = f2tf32(q2 - __uint_as_float(ahi[mt][2]));
                alo[mt][3] = f2tf32(q3 - __uint_as_float(ahi[mt][3]));
            }
            #pragma unroll
            for (int nt = 0; nt < 4; nt++) {
                int col = wn + nt * 8 + g;   // key index within tile
                bb[nt][0] = f2tf32(Ks[col * 68 + kk + tg    ]);
                bb[nt][1] = f2tf32(Ks[col * 68 + kk + tg + 4]);
            }
            #pragma unroll
            for (int mt = 0; mt < 2; mt++)
                #pragma unroll
                for (int nt = 0; nt < 4; nt++) {
                    mma_tf32(cs[mt][nt],
                             ahi[mt][0], ahi[mt][1], ahi[mt][2], ahi[mt][3],
                             bb[nt][0], bb[nt][1]);
                    mma_tf32(cs[mt][nt],
                             alo[mt][0], alo[mt][1], alo[mt][2], alo[mt][3],
                             bb[nt][0], bb[nt][1]);
                }
        }

        float rp[2][2] = {{0.f, 0.f}, {0.f, 0.f}};
        #pragma unroll
        for (int mt = 0; mt < 2; mt++) {
            #pragma unroll
            for (int nt = 0; nt < 4; nt++) {
                #pragma unroll
                for (int i = 0; i < 4; i++) {
                    int half = i >> 1;
                    int row_l = wm + mt * 16 + g + half * 8;
                    int col = wn + nt * 8 + tg * 2 + (i & 1);
                    int R = (qb * 128 + row_l) - (k0 + col);
                    float s = fmaxf(cs[mt][nt][i], 0.f);
                    float p = (R >= 0) ? __expf(s * Rs[R]) : 0.f;
                    Ps[row_l * 68 + col] = p;
                    rp[mt][half] += p;
                }
            }
        }
        #pragma unroll
        for (int mt = 0; mt < 2; mt++)
            #pragma unroll
            for (int half = 0; half < 2; half++) {
                float v = rp[mt][half];
                v += __shfl_xor_sync(0xffffffff, v, 1);
                v += __shfl_xor_sync(0xffffffff, v, 2);
                if (tg == 0)
                    atomicAdd(&Ls[wm + mt * 16 + g + half * 8], v);
            }
        __syncthreads();

        #pragma unroll
        for (int kk = 0; kk < 64; kk += 8) {
            unsigned pa[2][4], bb[4][2];
            #pragma unroll
            for (int mt = 0; mt < 2; mt++) {
                int row = wm + mt * 16 + g;
                pa[mt][0] = f2tf32(Ps[row * 68 + kk + tg]);
                pa[mt][1] = f2tf32(Ps[(row + 8) * 68 + kk + tg]);
                pa[mt][2] = f2tf32(Ps[row * 68 + kk + tg + 4]);
                pa[mt][3] = f2tf32(Ps[(row + 8) * 68 + kk + tg + 4]);
            }
            #pragma unroll
            for (int nt = 0; nt < 4; nt++) {
                int col = wn + nt * 8 + g;   // d index
                bb[nt][0] = f2tf32(Vs[(kk + tg) * 68 + col]);
                bb[nt][1] = f2tf32(Vs[(kk + tg + 4) * 68 + col]);
            }
            #pragma unroll
            for (int mt = 0; mt < 2; mt++)
                #pragma unroll
                for (int nt = 0; nt < 4; nt++)
                    mma_tf32(co[mt][nt],
                             pa[mt][0], pa[mt][1], pa[mt][2], pa[mt][3],
                             bb[nt][0], bb[nt][1]);
        }
        __syncthreads();
    }

    #pragma unroll
    for (int mt = 0; mt < 2; mt++) {
        #pragma unroll
        for (int half = 0; half < 2; half++) {
            int row_l = wm + mt * 16 + g + half * 8;
            float inv = 1.f / Ls[row_l];
            int n_ = qb * 128 + row_l;
            float* op = g_ctx + ((size_t)(b * NN + n_) * DOUT) + h * HD;
            #pragma unroll
            for (int nt = 0; nt < 4; nt++) {
                int col = wn + nt * 8 + tg * 2;
                op[col]     = co[mt][nt][half * 2 + 0] * inv;
                op[col + 1] = co[mt][nt][half * 2 + 1] * inv;
            }
        }
    }
}

// ---------------------------------------------------------------------------
extern "C" void kernel_launch(void* const* d_in, const int* in_sizes, int n_in,
                              void* d_out, int out_size)
{
    const float* x  = (const float*)d_in[0];
    const float* Wq = (const float*)d_in[1];
    const float* Wk = (const float*)d_in[2];
    const float* Wv = (const float*)d_in[3];
    const float* Wo = (const float*)d_in[4];
    const float* bo = (const float*)d_in[5];
    const float* w  = (const float*)d_in[6];
    const float* v  = (const float*)d_in[7];
    float* out = (float*)d_out;

    cudaFuncSetAttribute(attn_tc,
        cudaFuncAttributeMaxDynamicSharedMemorySize, ATTN_SMEM_BYTES);

    dim3 g1(DOUT / 128, (BB * NN) / 128, 3);
    qkv_gemm_tc<<<g1, 256>>>(x, Wq, Wk, Wv);

    dim3 g2(NN / 128, HH, BB);
    attn_tc<<<g2, 256, ATTN_SMEM_BYTES>>>(w, v);

    dim3 g3(DOUT / 128, (BB * NN) / 128, 1);
    out_gemm_tc<<<g3, 256>>>(Wo, bo, out);
}